// round 7
// baseline (speedup 1.0000x reference)
#include <cuda_runtime.h>
#include <math.h>
#include <stdint.h>

#define Vn 65536
#define En 262144
#define Gn 2048
#define NPG 32
#define H 200
#define DEG 4
#define NODE_IN 74
#define EDGE_IN 12
#define NLAYERS 5
#define TT 2
#define H3 600
#define H2 400

typedef unsigned long long ull;

// ---------------- device scratch ----------------
__device__ float g_h[Vn * H];
__device__ float g_eh[En * H];
__device__ float g_gf[Gn * H];
__device__ float g_a[Vn];
__device__ float g_hbar[Gn * H];
__device__ float g_ctx[Gn * H];
__device__ float g_gi[Gn * H3];
__device__ float g_gh[Gn * H3];
// packed-pair weights: out[k2*N + n] = (W[2k2][n], W[2k2+1][n])
__device__ ull g_Wgnn[NLAYERS * 100 * H];
__device__ ull g_Wpr[TT * 100 * H];
__device__ ull g_Wnode[37 * H];
__device__ ull g_Wedge[6 * H];
__device__ ull g_Wih2[TT * 100 * H3];
__device__ ull g_Whh2[TT * 100 * H3];

// ---------------- packed f32x2 helpers ----------------
__device__ __forceinline__ ull pk2(float lo, float hi) {
    ull r;
    asm("mov.b64 %0, {%1, %2};" : "=l"(r) : "f"(lo), "f"(hi));
    return r;
}
__device__ __forceinline__ void fma2(ull& d, ull a, ull b) {
    asm("fma.rn.f32x2 %0, %1, %2, %0;" : "+l"(d) : "l"(a), "l"(b));
}
__device__ __forceinline__ float hsum2(ull v) {
    float x, y;
    asm("mov.b64 {%0, %1}, %2;" : "=f"(x), "=f"(y) : "l"(v));
    return x + y;
}

// ---------------- weight packing ----------------
__global__ void k_packW(const float* __restrict__ W, ull* __restrict__ out,
                        int K2, int N) {
    int idx = blockIdx.x * blockDim.x + threadIdx.x;
    if (idx < K2 * N) {
        int k2 = idx / N, n = idx - k2 * N;
        out[idx] = pk2(W[(2 * k2) * N + n], W[(2 * k2 + 1) * N + n]);
    }
}
__global__ void k_packGRU(const float* __restrict__ W_ih,
                          const float* __restrict__ W_hh) {
    int idx = blockIdx.x * blockDim.x + threadIdx.x;
    if (idx < TT * 100 * H3) {
        int t = idx / (100 * H3);
        int r = idx - t * (100 * H3);
        int k2 = r / H3, j = r - k2 * H3;
        const float* wi = W_ih + t * H3 * H + j * H + 2 * k2;
        const float* wh = W_hh + t * H3 * H + j * H + 2 * k2;
        g_Wih2[idx] = pk2(wi[0], wi[1]);
        g_Whh2[idx] = pk2(wh[0], wh[1]);
    }
}

// ---------------- node embedding: 400 threads, 2 row-groups x 200 cols ----------------
__global__ __launch_bounds__(400, 2) void k_node_embed(const float* __restrict__ nf,
                                                       const float* __restrict__ b) {
    __shared__ __align__(16) float s[32][NODE_IN];
    int v0 = blockIdx.x * 32;
    int tid = threadIdx.x;
    for (int i = tid; i < 32 * NODE_IN; i += 400) {
        int r = i / NODE_IN, k = i - r * NODE_IN;
        s[r][k] = nf[(v0 + r) * NODE_IN + k];
    }
    __syncthreads();
    int q = tid / 200;
    int c = tid - q * 200;
    int r0 = q * 16;
    ull acc[16];
#pragma unroll
    for (int r = 0; r < 16; r++) acc[r] = 0ull;
    const ull* Wp = g_Wnode + c;
    for (int k2 = 0; k2 < 37; k2++) {
        ull w = __ldg(&Wp[k2 * H]);
#pragma unroll
        for (int r = 0; r < 16; r++) {
            ull a = *(const ull*)&s[r0 + r][2 * k2];
            fma2(acc[r], a, w);
        }
    }
    float bb = __ldg(&b[c]);
#pragma unroll
    for (int r = 0; r < 16; r++) g_h[(size_t)(v0 + r0 + r) * H + c] = hsum2(acc[r]) + bb;
}

// ---------------- edge embedding: 400 threads, 2 row-groups x 200 cols ----------------
__global__ __launch_bounds__(400, 2) void k_edge_embed(const float* __restrict__ ef,
                                                       const float* __restrict__ b) {
    __shared__ __align__(16) float s[32][EDGE_IN];
    int e0 = blockIdx.x * 32;
    int tid = threadIdx.x;
    for (int i = tid; i < 32 * EDGE_IN; i += 400) {
        int r = i / EDGE_IN, k = i - r * EDGE_IN;
        s[r][k] = ef[(e0 + r) * EDGE_IN + k];
    }
    __syncthreads();
    int q = tid / 200;
    int c = tid - q * 200;
    int r0 = q * 16;
    ull acc[16];
#pragma unroll
    for (int r = 0; r < 16; r++) acc[r] = 0ull;
    const ull* Wp = g_Wedge + c;
#pragma unroll
    for (int k2 = 0; k2 < 6; k2++) {
        ull w = __ldg(&Wp[k2 * H]);
#pragma unroll
        for (int r = 0; r < 16; r++) {
            ull a = *(const ull*)&s[r0 + r][2 * k2];
            fma2(acc[r], a, w);
        }
    }
    float bb = __ldg(&b[c]);
#pragma unroll
    for (int r = 0; r < 16; r++) g_eh[(size_t)(e0 + r0 + r) * H + c] = hsum2(acc[r]) + bb;
}

// ---------------- fused layer: 400 threads = 4 row-groups x 100 col-pairs ----------------
// block = 1 graph (32 nodes); GEMM thread owns 8 rows x 2 columns
__global__ __launch_bounds__(400, 3) void k_layer(const int* __restrict__ src,
                                                  const float* __restrict__ bias,
                                                  int layer) {
    extern __shared__ float smem[];
    float* s_h = smem;                       // [32][200]
    float* s_agg = s_h + NPG * H;            // [32][200]
    int* s_src = (int*)(s_agg + NPG * H);    // [128]

    int g = blockIdx.x;
    int tid = threadIdx.x;
    int vbase = g * NPG;

    // phase 1: stage h + src
    {
        const float4* gh4 = (const float4*)(g_h + (size_t)vbase * H);
        float4* sh4 = (float4*)s_h;
#pragma unroll
        for (int i = 0; i < 4; i++) sh4[tid + i * 400] = gh4[tid + i * 400];
        if (tid < NPG * DEG) s_src[tid] = src[vbase * DEG + tid] - vbase;
    }
    __syncthreads();

    // phase 2: edge softmax + aggregation (coalesced: c = i % 200)
    {
        const float* ehb = g_eh + (size_t)vbase * DEG * H;
#pragma unroll
        for (int ii = 0; ii < 16; ii++) {
            int i = tid + ii * 400;
            int v = i / H;
            int c = i - v * H;
            int e0 = v * DEG;
            float m0 = s_h[s_src[e0 + 0] * H + c] + __ldg(&ehb[(e0 + 0) * H + c]);
            float m1 = s_h[s_src[e0 + 1] * H + c] + __ldg(&ehb[(e0 + 1) * H + c]);
            float m2 = s_h[s_src[e0 + 2] * H + c] + __ldg(&ehb[(e0 + 2) * H + c]);
            float m3 = s_h[s_src[e0 + 3] * H + c] + __ldg(&ehb[(e0 + 3) * H + c]);
            float mx = fmaxf(fmaxf(m0, m1), fmaxf(m2, m3));
            float e0x = __expf(m0 - mx), e1x = __expf(m1 - mx);
            float e2x = __expf(m2 - mx), e3x = __expf(m3 - mx);
            float den = e0x + e1x + e2x + e3x;
            float agg = m0 * e0x + m1 * e1x + m2 * e2x + m3 * e3x;
            s_agg[v * H + c] = agg / den;
        }
    }
    __syncthreads();

    // phase 3: D[r0..r0+8, c0..c0+1] = agg @ W ; one LDG.128 covers both columns
    int q = tid / 100;          // row group -> rows [8q, 8q+8)
    int cp = tid - q * 100;     // column pair
    int c0 = 2 * cp;
    int r0 = q * 8;
    ull acc0[8], acc1[8];
#pragma unroll
    for (int r = 0; r < 8; r++) { acc0[r] = 0ull; acc1[r] = 0ull; }
    const ull* Wp = g_Wgnn + (size_t)layer * 100 * H + c0;
    const float* ag = s_agg + r0 * H;
    for (int k = 0; k < H; k += 4) {
        int k2 = k >> 1;
        ulonglong2 wA = *(const ulonglong2*)&Wp[k2 * H];        // k,k+1 for c0,c0+1
        ulonglong2 wB = *(const ulonglong2*)&Wp[(k2 + 1) * H];  // k+2,k+3
#pragma unroll
        for (int r = 0; r < 8; r++) {
            ulonglong2 a = *(const ulonglong2*)&ag[r * H + k];  // LDS.128 broadcast
            fma2(acc0[r], a.x, wA.x);
            fma2(acc1[r], a.x, wA.y);
            fma2(acc0[r], a.y, wB.x);
            fma2(acc1[r], a.y, wB.y);
        }
    }

    // phase 4: h = relu(D + bias) + h_old (float2 per row)
    float bb0 = __ldg(&bias[c0]);
    float bb1 = __ldg(&bias[c0 + 1]);
#pragma unroll
    for (int r = 0; r < 8; r++) {
        float o0 = hsum2(acc0[r]) + bb0;
        float o1 = hsum2(acc1[r]) + bb1;
        o0 = o0 > 0.f ? o0 : 0.f;
        o1 = o1 > 0.f ? o1 : 0.f;
        const float* hold = &s_h[(r0 + r) * H + c0];
        *(float2*)(g_h + (size_t)(vbase + r0 + r) * H + c0) =
            make_float2(o0 + hold[0], o1 + hold[1]);
    }
}

// ---------------- gf init ----------------
__global__ __launch_bounds__(200) void k_gf() {
    int g = blockIdx.x, c = threadIdx.x;
    float sum = 0.f;
    int base = g * NPG * H + c;
    for (int i = 0; i < NPG; i++) sum += g_h[base + i * H];
    g_gf[g * H + c] = sum;
}

// ---------------- readout attention ----------------
__global__ __launch_bounds__(256) void k_z(const float* __restrict__ lgW,
                                           const float* __restrict__ lgb, int t) {
    const float* w = lgW + t * H2;
    float bb = __ldg(&lgb[t]);
    int g = blockIdx.x;
    int tid = threadIdx.x;
    __shared__ float red[256];
    __shared__ float zs[NPG];

    float p = 0.f;
    if (tid < H) {
        float gfv = g_gf[g * H + tid];
        gfv = gfv > 0.f ? gfv : 0.f;
        p = gfv * w[tid];
    }
    red[tid] = p;
    __syncthreads();
    for (int off = 128; off > 0; off >>= 1) {
        if (tid < off) red[tid] += red[tid + off];
        __syncthreads();
    }
    float sg = red[0];

    int warp = tid >> 5, lane = tid & 31;
    for (int n = warp; n < NPG; n += 8) {
        int v = g * NPG + n;
        float sum = 0.f;
        for (int c = lane; c < H; c += 32) sum += g_h[v * H + c] * w[H + c];
        for (int off = 16; off; off >>= 1) sum += __shfl_xor_sync(0xffffffffu, sum, off);
        if (lane == 0) {
            float z = sum + sg + bb;
            zs[n] = z > 0.f ? z : 0.01f * z;
        }
    }
    __syncthreads();
    if (tid < 32) {
        float zv = zs[tid];
        float mx = zv;
        for (int off = 16; off; off >>= 1) mx = fmaxf(mx, __shfl_xor_sync(0xffffffffu, mx, off));
        float e = __expf(zv - mx);
        float den = e;
        for (int off = 16; off; off >>= 1) den += __shfl_xor_sync(0xffffffffu, den, off);
        g_a[g * NPG + tid] = e / den;
    }
}

// ---------------- hbar ----------------
__global__ __launch_bounds__(200) void k_hbar() {
    int g = blockIdx.x, c = threadIdx.x;
    float sum = 0.f;
    int vb = g * NPG;
    for (int i = 0; i < NPG; i++) sum += __ldg(&g_a[vb + i]) * g_h[(vb + i) * H + c];
    g_hbar[g * H + c] = sum;
}

// ---------------- ctx ----------------
__global__ __launch_bounds__(400, 2) void k_ctx(const float* __restrict__ prb, int t) {
    __shared__ __align__(16) float s[32][H];
    int g0 = blockIdx.x * 32;
    int tid = threadIdx.x;
    for (int i = tid; i < 32 * H; i += 400) {
        int r = i / H, k = i - r * H;
        s[r][k] = g_hbar[(g0 + r) * H + k];
    }
    __syncthreads();
    int q = tid / 200;
    int c = tid - q * 200;
    int r0 = q * 16;
    ull acc[16];
#pragma unroll
    for (int r = 0; r < 16; r++) acc[r] = 0ull;
    const ull* Wp = g_Wpr + (size_t)t * 100 * H + c;
    for (int k = 0; k < H; k += 4) {
        int k2 = k >> 1;
        ull w01 = __ldg(&Wp[k2 * H]);
        ull w23 = __ldg(&Wp[(k2 + 1) * H]);
#pragma unroll
        for (int r = 0; r < 16; r++) {
            ulonglong2 a = *(const ulonglong2*)&s[r0 + r][k];
            fma2(acc[r], a.x, w01);
            fma2(acc[r], a.y, w23);
        }
    }
    float bb = __ldg(&prb[t * H + c]);
#pragma unroll
    for (int r = 0; r < 16; r++) {
        float o = hsum2(acc[r]) + bb;
        o = o > 0.f ? o : expm1f(o);
        g_ctx[(size_t)(g0 + r0 + r) * H + c] = o;
    }
}

// ---------------- GRU gate GEMMs ----------------
__global__ __launch_bounds__(600) void k_gru(const float* __restrict__ bih,
                                             const float* __restrict__ bhh, int t) {
    __shared__ __align__(16) float sc[8][H];
    __shared__ __align__(16) float sh[8][H];
    int g0 = blockIdx.x * 8;
    int tid = threadIdx.x;
    for (int i = tid; i < 8 * H; i += 600) {
        int r = i / H, k = i - r * H;
        sc[r][k] = g_ctx[(g0 + r) * H + k];
        sh[r][k] = g_gf[(g0 + r) * H + k];
    }
    __syncthreads();
    int j = tid;
    const ull* Wi = g_Wih2 + (size_t)t * 100 * H3 + j;
    const ull* Wh = g_Whh2 + (size_t)t * 100 * H3 + j;
    ull ai[8], ah[8];
#pragma unroll
    for (int r = 0; r < 8; r++) { ai[r] = 0ull; ah[r] = 0ull; }
    for (int k = 0; k < H; k += 4) {
        int k2 = k >> 1;
        ull wi01 = __ldg(&Wi[k2 * H3]);
        ull wi23 = __ldg(&Wi[(k2 + 1) * H3]);
        ull wh01 = __ldg(&Wh[k2 * H3]);
        ull wh23 = __ldg(&Wh[(k2 + 1) * H3]);
#pragma unroll
        for (int r = 0; r < 8; r++) {
            ulonglong2 a = *(const ulonglong2*)&sc[r][k];
            fma2(ai[r], a.x, wi01);
            fma2(ai[r], a.y, wi23);
            ulonglong2 h4 = *(const ulonglong2*)&sh[r][k];
            fma2(ah[r], h4.x, wh01);
            fma2(ah[r], h4.y, wh23);
        }
    }
    float bi = __ldg(&bih[t * H3 + j]);
    float bh = __ldg(&bhh[t * H3 + j]);
#pragma unroll
    for (int r = 0; r < 8; r++) {
        g_gi[(size_t)(g0 + r) * H3 + j] = hsum2(ai[r]) + bi;
        g_gh[(size_t)(g0 + r) * H3 + j] = hsum2(ah[r]) + bh;
    }
}

// ---------------- GRU combine ----------------
__global__ __launch_bounds__(200) void k_gate() {
    int g = blockIdx.x, c = threadIdx.x;
    int base = g * H3;
    float ir = g_gi[base + c],          hr = g_gh[base + c];
    float iz = g_gi[base + H + c],      hz = g_gh[base + H + c];
    float in_ = g_gi[base + 2 * H + c], hn = g_gh[base + 2 * H + c];
    float r = 1.f / (1.f + expf(-(ir + hr)));
    float u = 1.f / (1.f + expf(-(iz + hz)));
    float n = tanhf(in_ + r * hn);
    int o = g * H + c;
    g_gf[o] = (1.f - u) * n + u * g_gf[o];
}

// ---------------- copy result ----------------
__global__ void k_copy(float* __restrict__ out, int n) {
    int i = blockIdx.x * blockDim.x + threadIdx.x;
    if (i < n) out[i] = g_gf[i];
}

// ---------------- launcher ----------------
extern "C" void kernel_launch(void* const* d_in, const int* in_sizes, int n_in,
                              void* d_out, int out_size) {
    const float* node_feat = (const float*)d_in[0];
    const float* edge_feat = (const float*)d_in[1];
    const int*   src       = (const int*)d_in[2];
    const float* node_W = (const float*)d_in[5];
    const float* node_b = (const float*)d_in[6];
    const float* edge_W = (const float*)d_in[7];
    const float* edge_b = (const float*)d_in[8];
    const float* gnn_W  = (const float*)d_in[9];
    const float* gnn_b  = (const float*)d_in[10];
    const float* lg_W   = (const float*)d_in[11];
    const float* lg_b   = (const float*)d_in[12];
    const float* pr_W   = (const float*)d_in[13];
    const float* pr_b   = (const float*)d_in[14];
    const float* W_ih   = (const float*)d_in[15];
    const float* W_hh   = (const float*)d_in[16];
    const float* b_ih   = (const float*)d_in[17];
    const float* b_hh   = (const float*)d_in[18];

    const int SMEM_LAYER = (2 * NPG * H + NPG * DEG) * 4;  // ~52KB
    cudaFuncSetAttribute(k_layer, cudaFuncAttributeMaxDynamicSharedMemorySize, SMEM_LAYER);

    ull* d_Wgnn;  cudaGetSymbolAddress((void**)&d_Wgnn, g_Wgnn);
    ull* d_Wpr;   cudaGetSymbolAddress((void**)&d_Wpr, g_Wpr);
    ull* d_Wnode; cudaGetSymbolAddress((void**)&d_Wnode, g_Wnode);
    ull* d_Wedge; cudaGetSymbolAddress((void**)&d_Wedge, g_Wedge);

    k_packW<<<(NLAYERS * 100 * H + 255) / 256, 256>>>(gnn_W, d_Wgnn, NLAYERS * 100, H);
    k_packW<<<(TT * 100 * H + 255) / 256, 256>>>(pr_W, d_Wpr, TT * 100, H);
    k_packW<<<(37 * H + 255) / 256, 256>>>(node_W, d_Wnode, 37, H);
    k_packW<<<(6 * H + 255) / 256, 256>>>(edge_W, d_Wedge, 6, H);
    k_packGRU<<<(TT * 100 * H3 + 255) / 256, 256>>>(W_ih, W_hh);

    k_node_embed<<<Vn / 32, 400>>>(node_feat, node_b);
    k_edge_embed<<<En / 32, 400>>>(edge_feat, edge_b);

    for (int i = 0; i < NLAYERS; i++) {
        k_layer<<<Gn, 400, SMEM_LAYER>>>(src, gnn_b + i * H, i);
    }

    k_gf<<<Gn, 200>>>();
    for (int t = 0; t < TT; t++) {
        k_z<<<Gn, 256>>>(lg_W, lg_b, t);
        k_hbar<<<Gn, 200>>>();
        k_ctx<<<Gn / 32, 400>>>(pr_b, t);
        k_gru<<<Gn / 8, 600>>>(b_ih, b_hh, t);
        k_gate<<<Gn, 200>>>();
    }

    k_copy<<<(Gn * H + 255) / 256, 256>>>((float*)d_out, Gn * H);
}